// round 7
// baseline (speedup 1.0000x reference)
#include <cuda_runtime.h>
#include <cstdint>
#include <cstddef>

#define DK  256
#define NB  32
#define NT  256
#define NHW 4096

// Scratch (static device globals; no allocation in kernel_launch)
__device__ float g_MT[DK * DK];      // MT[n][k] = sum_o Wq[o][k] * Wk[o][n]
__device__ float g_wv[DK];           // Wq^T bk
__device__ float g_wu[DK];           // Wk^T bq
__device__ float g_c;                // bq . bk
__device__ float g_G[NB * NT * DK];  // G = F_a @ (Wq^T Wk)
__device__ float g_v[NB * NT];       // v[t] = F_a[t] . g_wv
__device__ float g_psum[NB * NT * 32];

__device__ __forceinline__ uint32_t f2tf32(float f) {
    uint32_t u;
    asm("cvt.rna.tf32.f32 %0, %1;" : "=r"(u) : "f"(f));
    return u;
}
__device__ __forceinline__ float f2tf32f(float f) {
    return __uint_as_float(f2tf32(f));
}

// ---------------------------------------------------------------------------
__global__ void prep_mt(const float* __restrict__ Wq, const float* __restrict__ Wk) {
    __shared__ float sq[16][17], sk2[16][17];
    int k0 = blockIdx.x * 16, n0 = blockIdx.y * 16;
    int tx = threadIdx.x, ty = threadIdx.y;
    float a = 0.f;
    for (int o0 = 0; o0 < DK; o0 += 16) {
        sq[ty][tx]  = Wq[(o0 + ty) * DK + k0 + tx];
        sk2[ty][tx] = Wk[(o0 + ty) * DK + n0 + tx];
        __syncthreads();
#pragma unroll
        for (int o = 0; o < 16; o++) a += sq[o][tx] * sk2[o][ty];
        __syncthreads();
    }
    g_MT[(n0 + ty) * DK + (k0 + tx)] = a;
}

__global__ void prep_vec(const float* __restrict__ Wq, const float* __restrict__ Wk,
                         const float* __restrict__ bq, const float* __restrict__ bk) {
    __shared__ float r1[256], r2[256], r3[256];
    int k = blockIdx.x, o = threadIdx.x;
    r1[o] = Wq[o * DK + k] * bk[o];
    r2[o] = Wk[o * DK + k] * bq[o];
    r3[o] = (k == 0) ? bq[o] * bk[o] : 0.f;
    __syncthreads();
    for (int s = 128; s > 0; s >>= 1) {
        if (o < s) { r1[o] += r1[o + s]; r2[o] += r2[o + s]; r3[o] += r3[o + s]; }
        __syncthreads();
    }
    if (o == 0) {
        g_wv[k] = r1[0];
        g_wu[k] = r2[0];
        if (k == 0) g_c = r3[0];
    }
}

// ---------------------------------------------------------------------------
// tf32 mma GEMM with k-permuted smem layout:
//   element (row, c) of a 32-wide k-slice lives at col (c&3)*8 + (c>>2).
//   => each thread's mma fragments for the whole slice are contiguous float4s.
// Tiles: block 64(M) x 128(N), k-slice 32. 8 warps as 2(m) x 4(n), warp 32x32.
template <int MODE>
__global__ void __launch_bounds__(256, 2) gemm_kernel(
    const float* __restrict__ Aglob,   // MODE0: F_a
    const float* __restrict__ Bglob,   // MODE1: F_s
    const int*   __restrict__ Mask,    // MODE1: M_s flattened [B][HW]
    float*       __restrict__ Out)     // MODE1: d_out
{
    __shared__ float sA[64][36];
    __shared__ float sB[128][36];
    __shared__ float s_w[DK];
    __shared__ float s_u[128];
    __shared__ float s_vc[64];
    __shared__ float s_mask[128];
    __shared__ float s_ps[64][4];

    const int tid = threadIdx.x;
    const int s0 = blockIdx.x * 128;
    const int t0 = blockIdx.y * 64;
    const int b  = (MODE == 1) ? blockIdx.z : 0;

    const float* Abase;
    const float* Bbase;
    if (MODE == 0) {
        Abase = Aglob + (size_t)t0 * DK;
        Bbase = g_MT + (size_t)s0 * DK;
    } else {
        Abase = g_G + ((size_t)(b * NT + t0)) * DK;
        Bbase = Bglob + ((size_t)b * NHW + s0) * DK;
    }

    s_w[tid] = (MODE == 0) ? g_wv[tid] : g_wu[tid];
    if (MODE == 1 && tid < 128)
        s_mask[tid] = (Mask[(size_t)b * NHW + s0 + tid] != 0) ? 1.0f : 0.0f;

    const int warp = tid >> 5, lane = tid & 31;
    const int wm = warp >> 2, wn = warp & 3;
    const int g = lane >> 2, tg = lane & 3;

    float acc[2][4][4];
#pragma unroll
    for (int i = 0; i < 2; i++)
#pragma unroll
        for (int j = 0; j < 4; j++)
#pragma unroll
            for (int l = 0; l < 4; l++) acc[i][j][l] = 0.f;

    float fold = 0.f;  // MODE1: u[s] partial (tid<128); MODE0: v[t] partial (tid<64)

    const int arow = tid >> 2, acg = (tid & 3) * 8, at2 = (tid & 3) * 2;
    const int brow = tid >> 1, bcg = (tid & 1) * 16, bb4 = (tid & 1) * 4;

    for (int kk0 = 0; kk0 < DK; kk0 += 32) {
        __syncthreads();
        // ---- stage A slice 64x32, permuted + tf32-rounded (4x float2 STS) ----
        {
            const float* src = Abase + (size_t)arow * DK + kk0 + acg;
            float4 v0 = *(const float4*)(src);
            float4 v1 = *(const float4*)(src + 4);
            *(float2*)&sA[arow][ 0 + at2] = make_float2(f2tf32f(v0.x), f2tf32f(v1.x));
            *(float2*)&sA[arow][ 8 + at2] = make_float2(f2tf32f(v0.y), f2tf32f(v1.y));
            *(float2*)&sA[arow][16 + at2] = make_float2(f2tf32f(v0.z), f2tf32f(v1.z));
            *(float2*)&sA[arow][24 + at2] = make_float2(f2tf32f(v0.w), f2tf32f(v1.w));
        }
        // ---- stage B slice 128x32, permuted + tf32-rounded (8x float2 STS) ----
        {
            const float* src = Bbase + (size_t)brow * DK + kk0 + bcg;
            float4 w0 = *(const float4*)(src);
            float4 w1 = *(const float4*)(src + 4);
            float4 w2 = *(const float4*)(src + 8);
            float4 w3 = *(const float4*)(src + 12);
            *(float2*)&sB[brow][ 0 + bb4    ] = make_float2(f2tf32f(w0.x), f2tf32f(w1.x));
            *(float2*)&sB[brow][ 8 + bb4    ] = make_float2(f2tf32f(w0.y), f2tf32f(w1.y));
            *(float2*)&sB[brow][16 + bb4    ] = make_float2(f2tf32f(w0.z), f2tf32f(w1.z));
            *(float2*)&sB[brow][24 + bb4    ] = make_float2(f2tf32f(w0.w), f2tf32f(w1.w));
            *(float2*)&sB[brow][ 0 + bb4 + 2] = make_float2(f2tf32f(w2.x), f2tf32f(w3.x));
            *(float2*)&sB[brow][ 8 + bb4 + 2] = make_float2(f2tf32f(w2.y), f2tf32f(w3.y));
            *(float2*)&sB[brow][16 + bb4 + 2] = make_float2(f2tf32f(w2.z), f2tf32f(w3.z));
            *(float2*)&sB[brow][24 + bb4 + 2] = make_float2(f2tf32f(w2.w), f2tf32f(w3.w));
        }
        __syncthreads();

        // ---- bias folds (permuted read: col p holds k = (p&7)*4 + (p>>3)) ----
        if (MODE == 1) {
            if (tid < 128) {
                float a = 0.f;
#pragma unroll
                for (int p = 0; p < 32; p++)
                    a += sB[tid][p] * s_w[kk0 + (p & 7) * 4 + (p >> 3)];
                fold += a;
            }
        } else {
            if (blockIdx.x == 0 && tid < 64) {
                float a = 0.f;
#pragma unroll
                for (int p = 0; p < 32; p++)
                    a += sA[tid][p] * s_w[kk0 + (p & 7) * 4 + (p >> 3)];
                fold += a;
            }
        }

        // ---- batched fragment loads: 16x LDS.128 covering the whole 32-k slice ----
        // half h covers kk = 16h + {0,8}; component x,y -> kk+0; z,w -> kk+8.
        float4 aA[2][2][2];  // [h][mt][row 0:+g, 1:+g+8]
        float4 bB[2][4];     // [h][nt]
#pragma unroll
        for (int h = 0; h < 2; h++) {
#pragma unroll
            for (int mt = 0; mt < 2; mt++) {
                int r = wm * 32 + mt * 16;
                aA[h][mt][0] = *(const float4*)&sA[r + g    ][tg * 8 + h * 4];
                aA[h][mt][1] = *(const float4*)&sA[r + g + 8][tg * 8 + h * 4];
            }
#pragma unroll
            for (int nt = 0; nt < 4; nt++) {
                bB[h][nt] = *(const float4*)&sB[wn * 32 + nt * 8 + g][tg * 8 + h * 4];
            }
        }

        // ---- unbroken chain of 32 mmas ----
#pragma unroll
        for (int h = 0; h < 2; h++) {
#pragma unroll
            for (int s = 0; s < 2; s++) {
#pragma unroll
                for (int mt = 0; mt < 2; mt++) {
                    uint32_t a0, a1, a2, a3;
                    if (s == 0) {
                        a0 = __float_as_uint(aA[h][mt][0].x);
                        a1 = __float_as_uint(aA[h][mt][1].x);
                        a2 = __float_as_uint(aA[h][mt][0].y);
                        a3 = __float_as_uint(aA[h][mt][1].y);
                    } else {
                        a0 = __float_as_uint(aA[h][mt][0].z);
                        a1 = __float_as_uint(aA[h][mt][1].z);
                        a2 = __float_as_uint(aA[h][mt][0].w);
                        a3 = __float_as_uint(aA[h][mt][1].w);
                    }
#pragma unroll
                    for (int nt = 0; nt < 4; nt++) {
                        uint32_t b0, b1;
                        if (s == 0) {
                            b0 = __float_as_uint(bB[h][nt].x);
                            b1 = __float_as_uint(bB[h][nt].y);
                        } else {
                            b0 = __float_as_uint(bB[h][nt].z);
                            b1 = __float_as_uint(bB[h][nt].w);
                        }
                        asm volatile(
                            "mma.sync.aligned.m16n8k8.row.col.f32.tf32.tf32.f32 "
                            "{%0,%1,%2,%3}, {%4,%5,%6,%7}, {%8,%9}, {%0,%1,%2,%3};"
                            : "+f"(acc[mt][nt][0]), "+f"(acc[mt][nt][1]),
                              "+f"(acc[mt][nt][2]), "+f"(acc[mt][nt][3])
                            : "r"(a0), "r"(a1), "r"(a2), "r"(a3),
                              "r"(b0), "r"(b1));
                    }
                }
            }
        }
    }

    if (MODE == 0) {
        if (blockIdx.x == 0 && tid < 64) g_v[t0 + tid] = fold;
#pragma unroll
        for (int mt = 0; mt < 2; mt++)
#pragma unroll
            for (int nt = 0; nt < 4; nt++) {
                int r0 = t0 + wm * 32 + mt * 16 + g;
                int c  = s0 + wn * 32 + nt * 8 + 2 * tg;
                float* o0 = g_G + (size_t)r0 * DK + c;
                *(float2*)o0 = make_float2(acc[mt][nt][0], acc[mt][nt][1]);
                *(float2*)(o0 + (size_t)8 * DK) = make_float2(acc[mt][nt][2], acc[mt][nt][3]);
            }
    } else {
        if (tid < 128) s_u[tid] = fold;
        if (tid < 64)  s_vc[tid] = g_v[b * NT + t0 + tid] + g_c;
        __syncthreads();

#pragma unroll
        for (int mt = 0; mt < 2; mt++) {
            int rl0 = wm * 32 + mt * 16 + g;
            int rl1 = rl0 + 8;
            float rp0 = 0.f, rp1 = 0.f;
#pragma unroll
            for (int nt = 0; nt < 4; nt++) {
                int c = wn * 32 + nt * 8 + 2 * tg;
                float u0 = s_u[c], u1 = s_u[c + 1];
                float m0 = s_mask[c], m1 = s_mask[c + 1];
                float v0 = s_vc[rl0], v1 = s_vc[rl1];
                float e00 = m0 * __expf((acc[mt][nt][0] + u0 + v0) * 0.0625f);
                float e01 = m1 * __expf((acc[mt][nt][1] + u1 + v0) * 0.0625f);
                float e10 = m0 * __expf((acc[mt][nt][2] + u0 + v1) * 0.0625f);
                float e11 = m1 * __expf((acc[mt][nt][3] + u1 + v1) * 0.0625f);
                size_t base0 = ((size_t)(b * NT + t0 + rl0)) * NHW + s0 + c;
                size_t base1 = ((size_t)(b * NT + t0 + rl1)) * NHW + s0 + c;
                *(float2*)(Out + base0) = make_float2(e00, e01);
                *(float2*)(Out + base1) = make_float2(e10, e11);
                rp0 += e00 + e01;
                rp1 += e10 + e11;
            }
            rp0 += __shfl_xor_sync(0xffffffffu, rp0, 1);
            rp0 += __shfl_xor_sync(0xffffffffu, rp0, 2);
            rp1 += __shfl_xor_sync(0xffffffffu, rp1, 1);
            rp1 += __shfl_xor_sync(0xffffffffu, rp1, 2);
            if (tg == 0) { s_ps[rl0][wn] = rp0; s_ps[rl1][wn] = rp1; }
        }
        __syncthreads();
        if (tid < 64) {
            g_psum[((size_t)(b * NT + t0 + tid)) * 32 + blockIdx.x] =
                (s_ps[tid][0] + s_ps[tid][1]) + (s_ps[tid][2] + s_ps[tid][3]);
        }
    }
}

// ---------------------------------------------------------------------------
__global__ void __launch_bounds__(256) scale_kernel(float* __restrict__ out) {
    int row = blockIdx.x;
    __shared__ float sinv;
    if (threadIdx.x < 32) {
        float p = g_psum[(size_t)row * 32 + threadIdx.x];
#pragma unroll
        for (int o = 16; o; o >>= 1) p += __shfl_xor_sync(0xffffffffu, p, o);
        if (threadIdx.x == 0) sinv = 1.0f / p;
    }
    __syncthreads();
    float inv = sinv;
    float4* o4 = (float4*)(out + (size_t)row * NHW);
#pragma unroll
    for (int i = 0; i < 4; i++) {
        int idx = threadIdx.x + i * 256;
        float4 v = o4[idx];
        v.x *= inv; v.y *= inv; v.z *= inv; v.w *= inv;
        o4[idx] = v;
    }
}

// ---------------------------------------------------------------------------
extern "C" void kernel_launch(void* const* d_in, const int* in_sizes, int n_in,
                              void* d_out, int out_size) {
    (void)in_sizes; (void)n_in; (void)out_size;
    const float* F_a = (const float*)d_in[0];
    const float* F_s = (const float*)d_in[1];
    const int*   M_s = (const int*)  d_in[2];
    const float* Wq  = (const float*)d_in[3];
    const float* bq  = (const float*)d_in[4];
    const float* Wk  = (const float*)d_in[5];
    const float* bk  = (const float*)d_in[6];
    float* out = (float*)d_out;

    prep_mt<<<dim3(16, 16), dim3(16, 16)>>>(Wq, Wk);
    prep_vec<<<DK, 256>>>(Wq, Wk, bq, bk);
    gemm_kernel<0><<<dim3(2, 128, 1), 256>>>(F_a, nullptr, nullptr, nullptr);
    gemm_kernel<1><<<dim3(32, 4, 32), 256>>>(nullptr, F_s, M_s, out);
    scale_kernel<<<NB * NT, 256>>>(out);
}

// round 10
// speedup vs baseline: 1.1185x; 1.1185x over previous
#include <cuda_runtime.h>
#include <cstdint>
#include <cstddef>

#define DK  256
#define NB  32
#define NT  256
#define NHW 4096

// Scratch (static device globals; no allocation in kernel_launch)
__device__ float g_MT[DK * DK];      // MT[n][k] = sum_o Wq[o][k] * Wk[o][n]
__device__ float g_wv[DK];           // Wq^T bk
__device__ float g_wu[DK];           // Wk^T bq
__device__ float g_c;                // bq . bk
__device__ float g_G[NB * NT * DK];  // G = F_a @ (Wq^T Wk)
__device__ float g_v[NB * NT];       // v[t] = F_a[t] . g_wv
__device__ float g_psum[NB * NT * 16];

__device__ __forceinline__ uint32_t f2tf32(float f) {
    uint32_t u;
    asm("cvt.rna.tf32.f32 %0, %1;" : "=r"(u) : "f"(f));
    return u;
}
__device__ __forceinline__ float f2tf32f(float f) {
    return __uint_as_float(f2tf32(f));
}

// ---------------------------------------------------------------------------
__global__ void prep_mt(const float* __restrict__ Wq, const float* __restrict__ Wk) {
    __shared__ float sq[16][17], sk2[16][17];
    int k0 = blockIdx.x * 16, n0 = blockIdx.y * 16;
    int tx = threadIdx.x, ty = threadIdx.y;
    float a = 0.f;
    for (int o0 = 0; o0 < DK; o0 += 16) {
        sq[ty][tx]  = Wq[(o0 + ty) * DK + k0 + tx];
        sk2[ty][tx] = Wk[(o0 + ty) * DK + n0 + tx];
        __syncthreads();
#pragma unroll
        for (int o = 0; o < 16; o++) a += sq[o][tx] * sk2[o][ty];
        __syncthreads();
    }
    g_MT[(n0 + ty) * DK + (k0 + tx)] = a;
}

__global__ void prep_vec(const float* __restrict__ Wq, const float* __restrict__ Wk,
                         const float* __restrict__ bq, const float* __restrict__ bk) {
    __shared__ float r1[256], r2[256], r3[256];
    int k = blockIdx.x, o = threadIdx.x;
    r1[o] = Wq[o * DK + k] * bk[o];
    r2[o] = Wk[o * DK + k] * bq[o];
    r3[o] = (k == 0) ? bq[o] * bk[o] : 0.f;
    __syncthreads();
    for (int s = 128; s > 0; s >>= 1) {
        if (o < s) { r1[o] += r1[o + s]; r2[o] += r2[o + s]; r3[o] += r3[o + s]; }
        __syncthreads();
    }
    if (o == 0) {
        g_wv[k] = r1[0];
        g_wu[k] = r2[0];
        if (k == 0) g_c = r3[0];
    }
}

// ---------------------------------------------------------------------------
// tf32 mma GEMM, CTA tile 128(M) x 256(N), k-slice 32.
// 8 warps as 2(m) x 4(n); warp tile 64x64 = 4(m16) x 8(n8) mmas per k8.
// LDS bytes per mma halved vs 32x32 warp tiles (the R5/R6 L1 wall).
// Smem layout (floats), stride 36 for conflict-free (4g+tg) fragment reads:
static const int OFF_A    = 0;                 // 128*36 = 4608
static const int OFF_B    = 4608;              // 256*36 = 9216
static const int OFF_W    = 13824;             // 256
static const int OFF_U    = 14080;             // 256
static const int OFF_VC   = 14336;             // 128
static const int OFF_MASK = 14464;             // 256
static const int OFF_PS   = 14720;             // 128*4 = 512
static const int SMEM_FLOATS = 15232;          // 60928 bytes

template <int MODE>
__global__ void __launch_bounds__(256, 1) gemm_kernel(
    const float* __restrict__ Aglob,   // MODE0: F_a
    const float* __restrict__ Bglob,   // MODE1: F_s
    const int*   __restrict__ Mask,    // MODE1: M_s flattened [B][HW]
    float*       __restrict__ Out)     // MODE1: d_out
{
    extern __shared__ float smem[];
    float (*sA)[36]  = (float (*)[36])(smem + OFF_A);
    float (*sB)[36]  = (float (*)[36])(smem + OFF_B);
    float* s_w    = smem + OFF_W;
    float* s_u    = smem + OFF_U;
    float* s_vc   = smem + OFF_VC;
    float* s_mask = smem + OFF_MASK;
    float (*s_ps)[4] = (float (*)[4])(smem + OFF_PS);

    const int tid = threadIdx.x;
    const int s0 = blockIdx.x * 256;
    const int t0 = blockIdx.y * 128;
    const int b  = (MODE == 1) ? blockIdx.z : 0;

    const float* Abase;
    const float* Bbase;
    if (MODE == 0) {
        Abase = Aglob + (size_t)t0 * DK;
        Bbase = g_MT + (size_t)s0 * DK;
    } else {
        Abase = g_G + ((size_t)(b * NT + t0)) * DK;
        Bbase = Bglob + ((size_t)b * NHW + s0) * DK;
    }

    s_w[tid] = (MODE == 0) ? g_wv[tid] : g_wu[tid];
    if (MODE == 1)
        s_mask[tid] = (Mask[(size_t)b * NHW + s0 + tid] != 0) ? 1.0f : 0.0f;

    const int warp = tid >> 5, lane = tid & 31;
    const int wm = warp >> 2, wn = warp & 3;   // 2 x 4 warp grid
    const int g = lane >> 2, tg = lane & 3;

    float acc[4][8][4];
#pragma unroll
    for (int i = 0; i < 4; i++)
#pragma unroll
        for (int j = 0; j < 8; j++)
#pragma unroll
            for (int l = 0; l < 4; l++) acc[i][j][l] = 0.f;

    float fold = 0.f;  // MODE1: u[s] (all 256); MODE0: v[t] (tid<128)

    const int arow = tid >> 1, acg = (tid & 1) * 16;

    for (int kk0 = 0; kk0 < DK; kk0 += 32) {
        __syncthreads();
        // ---- stage A slice 128x32 (tf32-rounded): thread = half-row ----
        {
            const float* src = Abase + (size_t)arow * DK + kk0 + acg;
#pragma unroll
            for (int j = 0; j < 4; j++) {
                float4 v = *(const float4*)(src + 4 * j);
                sA[arow][acg + 4 * j + 0] = f2tf32f(v.x);
                sA[arow][acg + 4 * j + 1] = f2tf32f(v.y);
                sA[arow][acg + 4 * j + 2] = f2tf32f(v.z);
                sA[arow][acg + 4 * j + 3] = f2tf32f(v.w);
            }
        }
        // ---- stage B slice 256x32 (tf32-rounded): thread = full row ----
        {
            const float* src = Bbase + (size_t)tid * DK + kk0;
#pragma unroll
            for (int j = 0; j < 8; j++) {
                float4 v = *(const float4*)(src + 4 * j);
                sB[tid][4 * j + 0] = f2tf32f(v.x);
                sB[tid][4 * j + 1] = f2tf32f(v.y);
                sB[tid][4 * j + 2] = f2tf32f(v.z);
                sB[tid][4 * j + 3] = f2tf32f(v.w);
            }
        }
        __syncthreads();

        // ---- bias folds ----
        if (MODE == 1) {
            float a = 0.f;
#pragma unroll
            for (int k = 0; k < 32; k++) a += sB[tid][k] * s_w[kk0 + k];
            fold += a;
        } else {
            if (tid < 128) {
                float a = 0.f;
#pragma unroll
                for (int k = 0; k < 32; k++) a += sA[tid][k] * s_w[kk0 + k];
                fold += a;
            }
        }

        // ---- mma: 4 k8 steps, 32 mmas each ----
#pragma unroll
        for (int kk = 0; kk < 32; kk += 8) {
            uint32_t aF[4][4];
            uint32_t bF[8][2];
#pragma unroll
            for (int mt = 0; mt < 4; mt++) {
                int r = wm * 64 + mt * 16;
                aF[mt][0] = __float_as_uint(sA[r + g    ][kk + tg    ]);
                aF[mt][1] = __float_as_uint(sA[r + g + 8][kk + tg    ]);
                aF[mt][2] = __float_as_uint(sA[r + g    ][kk + tg + 4]);
                aF[mt][3] = __float_as_uint(sA[r + g + 8][kk + tg + 4]);
            }
#pragma unroll
            for (int nt = 0; nt < 8; nt++) {
                int cb = wn * 64 + nt * 8;
                bF[nt][0] = __float_as_uint(sB[cb + g][kk + tg    ]);
                bF[nt][1] = __float_as_uint(sB[cb + g][kk + tg + 4]);
            }
#pragma unroll
            for (int mt = 0; mt < 4; mt++)
#pragma unroll
                for (int nt = 0; nt < 8; nt++) {
                    asm volatile(
                        "mma.sync.aligned.m16n8k8.row.col.f32.tf32.tf32.f32 "
                        "{%0,%1,%2,%3}, {%4,%5,%6,%7}, {%8,%9}, {%0,%1,%2,%3};"
                        : "+f"(acc[mt][nt][0]), "+f"(acc[mt][nt][1]),
                          "+f"(acc[mt][nt][2]), "+f"(acc[mt][nt][3])
                        : "r"(aF[mt][0]), "r"(aF[mt][1]), "r"(aF[mt][2]), "r"(aF[mt][3]),
                          "r"(bF[nt][0]), "r"(bF[nt][1]));
                }
        }
    }

    if (MODE == 0) {
        if (tid < 128) g_v[t0 + tid] = fold;
#pragma unroll
        for (int mt = 0; mt < 4; mt++)
#pragma unroll
            for (int nt = 0; nt < 8; nt++) {
                int r0 = t0 + wm * 64 + mt * 16 + g;
                int c  = s0 + wn * 64 + nt * 8 + 2 * tg;
                float* o0 = g_G + (size_t)r0 * DK + c;
                *(float2*)o0 = make_float2(acc[mt][nt][0], acc[mt][nt][1]);
                *(float2*)(o0 + (size_t)8 * DK) = make_float2(acc[mt][nt][2], acc[mt][nt][3]);
            }
    } else {
        s_u[tid] = fold;
        if (tid < 128) s_vc[tid] = g_v[b * NT + t0 + tid] + g_c;
        __syncthreads();

#pragma unroll
        for (int mt = 0; mt < 4; mt++) {
            int rl0 = wm * 64 + mt * 16 + g;
            int rl1 = rl0 + 8;
            float rp0 = 0.f, rp1 = 0.f;
#pragma unroll
            for (int nt = 0; nt < 8; nt++) {
                int c = wn * 64 + nt * 8 + 2 * tg;
                float u0 = s_u[c], u1 = s_u[c + 1];
                float m0 = s_mask[c], m1 = s_mask[c + 1];
                float v0 = s_vc[rl0], v1 = s_vc[rl1];
                float e00 = m0 * __expf((acc[mt][nt][0] + u0 + v0) * 0.0625f);
                float e01 = m1 * __expf((acc[mt][nt][1] + u1 + v0) * 0.0625f);
                float e10 = m0 * __expf((acc[mt][nt][2] + u0 + v1) * 0.0625f);
                float e11 = m1 * __expf((acc[mt][nt][3] + u1 + v1) * 0.0625f);
                size_t base0 = ((size_t)(b * NT + t0 + rl0)) * NHW + s0 + c;
                size_t base1 = ((size_t)(b * NT + t0 + rl1)) * NHW + s0 + c;
                *(float2*)(Out + base0) = make_float2(e00, e01);
                *(float2*)(Out + base1) = make_float2(e10, e11);
                rp0 += e00 + e01;
                rp1 += e10 + e11;
            }
            rp0 += __shfl_xor_sync(0xffffffffu, rp0, 1);
            rp0 += __shfl_xor_sync(0xffffffffu, rp0, 2);
            rp1 += __shfl_xor_sync(0xffffffffu, rp1, 1);
            rp1 += __shfl_xor_sync(0xffffffffu, rp1, 2);
            if (tg == 0) { s_ps[rl0][wn] = rp0; s_ps[rl1][wn] = rp1; }
        }
        __syncthreads();
        if (tid < 128) {
            g_psum[((size_t)(b * NT + t0 + tid)) * 16 + blockIdx.x] =
                (s_ps[tid][0] + s_ps[tid][1]) + (s_ps[tid][2] + s_ps[tid][3]);
        }
    }
}

// ---------------------------------------------------------------------------
__global__ void __launch_bounds__(256) scale_kernel(float* __restrict__ out) {
    int row = blockIdx.x;
    __shared__ float sinv;
    if (threadIdx.x < 32) {
        float p = (threadIdx.x < 16) ? g_psum[(size_t)row * 16 + threadIdx.x] : 0.f;
#pragma unroll
        for (int o = 8; o; o >>= 1) p += __shfl_xor_sync(0xffffffffu, p, o);
        if (threadIdx.x == 0) sinv = 1.0f / p;
    }
    __syncthreads();
    float inv = sinv;
    float4* o4 = (float4*)(out + (size_t)row * NHW);
#pragma unroll
    for (int i = 0; i < 4; i++) {
        int idx = threadIdx.x + i * 256;
        float4 v = o4[idx];
        v.x *= inv; v.y *= inv; v.z *= inv; v.w *= inv;
        o4[idx] = v;
    }
}

// ---------------------------------------------------------------------------
extern "C" void kernel_launch(void* const* d_in, const int* in_sizes, int n_in,
                              void* d_out, int out_size) {
    (void)in_sizes; (void)n_in; (void)out_size;
    const float* F_a = (const float*)d_in[0];
    const float* F_s = (const float*)d_in[1];
    const int*   M_s = (const int*)  d_in[2];
    const float* Wq  = (const float*)d_in[3];
    const float* bq  = (const float*)d_in[4];
    const float* Wk  = (const float*)d_in[5];
    const float* bk  = (const float*)d_in[6];
    float* out = (float*)d_out;

    // Unconditional (no static guard; deterministic, idempotent, capture-safe).
    const int smem_bytes = SMEM_FLOATS * 4;
    cudaFuncSetAttribute(gemm_kernel<0>, cudaFuncAttributeMaxDynamicSharedMemorySize, smem_bytes);
    cudaFuncSetAttribute(gemm_kernel<1>, cudaFuncAttributeMaxDynamicSharedMemorySize, smem_bytes);

    prep_mt<<<dim3(16, 16), dim3(16, 16)>>>(Wq, Wk);
    prep_vec<<<DK, 256>>>(Wq, Wk, bq, bk);
    gemm_kernel<0><<<dim3(1, 64, 1), 256, smem_bytes>>>(F_a, nullptr, nullptr, nullptr);
    gemm_kernel<1><<<dim3(16, 2, 32), 256, smem_bytes>>>(nullptr, F_s, M_s, out);
    scale_kernel<<<NB * NT, 256>>>(out);
}